// round 2
// baseline (speedup 1.0000x reference)
#include <cuda_runtime.h>
#include <cstdint>

// Problem dims (fixed by the dataset)
#define Bv 8
#define Cv 64
#define Hv 256
#define Wv 256
#define HW (Hv * Wv)          // 65536
#define CI_CHUNK 8
#define EPSV 1e-5f

// ---------------- scratch (no allocations allowed) ----------------
__device__ float g_colsum[Bv * Cv * Wv];   // sum over h of x  [b,c,w]
__device__ float g_fsum[Bv * Cv];
__device__ float g_scores[Bv * Cv];

// ---------------- f32x2 helpers ----------------
__device__ __forceinline__ unsigned long long pk2(float lo, float hi) {
    unsigned long long r;
    asm("mov.b64 %0, {%1, %2};" : "=l"(r) : "f"(lo), "f"(hi));
    return r;
}
__device__ __forceinline__ void unpk2(unsigned long long v, float& lo, float& hi) {
    asm("mov.b64 {%0, %1}, %2;" : "=f"(lo), "=f"(hi) : "l"(v));
}
__device__ __forceinline__ unsigned long long fma2(unsigned long long a,
                                                   unsigned long long b,
                                                   unsigned long long c) {
    unsigned long long d;
    asm("fma.rn.f32x2 %0, %1, %2, %3;" : "=l"(d) : "l"(a), "l"(b), "l"(c));
    return d;
}

// ---------------- kernel 1: column sums of x ----------------
// grid = B*C blocks, 256 threads (one per w). 134 MB streaming read.
__global__ void k_colsum(const float* __restrict__ x) {
    int bc = blockIdx.x;
    int w = threadIdx.x;
    const float* p = x + (size_t)bc * HW + w;
    float s0 = 0.f, s1 = 0.f, s2 = 0.f, s3 = 0.f;
    #pragma unroll 4
    for (int h = 0; h < Hv; h += 4) {
        s0 += p[(h + 0) * Wv];
        s1 += p[(h + 1) * Wv];
        s2 += p[(h + 2) * Wv];
        s3 += p[(h + 3) * Wv];
    }
    g_colsum[bc * Wv + w] = (s0 + s1) + (s2 + s3);
}

// ---------------- kernel 2: f_sum[b,c] via row-sum identity ----------------
// sum_h conv(x,w)[.,w'] uses only colsum S, first row, last row of x.
// grid = (C, B), 256 threads (one per w).
__global__ void k_fsum(const float* __restrict__ x,
                       const float* __restrict__ wq,
                       const float* __restrict__ wk) {
    int c = blockIdx.x, b = blockIdx.y;
    int w = threadIdx.x;
    __shared__ float wqs[576];
    __shared__ float wks[576];
    __shared__ float red[256];
    for (int i = threadIdx.x; i < 576; i += 256) {
        wqs[i] = wq[c * 576 + i];
        wks[i] = wk[c * 576 + i];
    }
    __syncthreads();

    float sq = 0.f, sk = 0.f;
    for (int ci = 0; ci < Cv; ci++) {
        const float* Sc = g_colsum + (b * Cv + ci) * Wv;
        const float* xf = x + (size_t)(b * Cv + ci) * HW;           // row 0
        const float* xl = xf + (Hv - 1) * Wv;                       // row H-1
        const float* q9 = wqs + ci * 9;
        const float* K9 = wks + ci * 9;
        #pragma unroll
        for (int dw = 0; dw < 3; dw++) {
            int wp = w + dw - 1;
            if ((unsigned)wp < (unsigned)Wv) {
                float s = Sc[wp], t = xl[wp], f = xf[wp];
                float q0 = q9[dw], q1 = q9[3 + dw], q2 = q9[6 + dw];
                float k0 = K9[dw], k1 = K9[3 + dw], k2 = K9[6 + dw];
                sq += s * (q0 + q1 + q2) - t * q0 - f * q2;
                sk += s * (k0 + k1 + k2) - t * k0 - f * k2;
            }
        }
    }
    red[w] = sq * sk;
    __syncthreads();
    for (int s = 128; s > 0; s >>= 1) {
        if (w < s) red[w] += red[w + s];
        __syncthreads();
    }
    if (w == 0) g_fsum[b * Cv + c] = red[0] * 0.0625f;   // 1/sqrt(256)
}

// ---------------- kernel 3: softmax over channels ----------------
// grid = B blocks, 64 threads.
__global__ void k_softmax() {
    int b = blockIdx.x, t = threadIdx.x;
    __shared__ float sm[64];
    float v = g_fsum[b * Cv + t];
    sm[t] = v;
    __syncthreads();
    for (int s = 32; s > 0; s >>= 1) {
        if (t < s) sm[t] = fmaxf(sm[t], sm[t + s]);
        __syncthreads();
    }
    float m = sm[0];
    __syncthreads();
    float e = expf(v - m);
    sm[t] = e;
    __syncthreads();
    for (int s = 32; s > 0; s >>= 1) {
        if (t < s) sm[t] += sm[t + s];
        __syncthreads();
    }
    g_scores[b * Cv + t] = e / sm[0];
}

// ---------------- kernel 4: fused conv3x3(wv) + epilogue ----------------
// out = relu( (score*inv) * fv + inv * x + (beta - mean*inv) )
// Block: one (b, h) row, all 64 couts, W=256 columns. 512 threads:
//   tx = lane (32 w-lanes), ty = 0..15 -> couts ty*4 .. ty*4+3.
// Each thread: 4 couts x 8 w positions, packed as 4 f32x2 pairs (w, w+128).
__global__ void __launch_bounds__(512, 1)
k_convv(const float* __restrict__ x,
        const float* __restrict__ wv,
        const float* __restrict__ gamma,
        const float* __restrict__ beta,
        const float* __restrict__ rmean,
        const float* __restrict__ rvar,
        float* __restrict__ out) {
    __shared__ float xs[CI_CHUNK * 3 * 258];    // [ci][row][col(-1..256)]
    __shared__ float ws[CI_CHUNK * 9 * 64];     // [(ci*9 + dh*3 + dw)][cout]

    const int h = blockIdx.x;
    const int b = blockIdx.y;
    const int tid = threadIdx.x;
    const int tx = tid & 31;
    const int ty = tid >> 5;
    const int cbase = ty * 4;

    unsigned long long acc[4][4];
    #pragma unroll
    for (int k = 0; k < 4; k++)
        #pragma unroll
        for (int a = 0; a < 4; a++) acc[k][a] = 0ull;

    for (int cc = 0; cc < Cv / CI_CHUNK; cc++) {
        __syncthreads();
        // ---- load x tile: 8 ci x 3 rows x 258 cols (zero-padded) ----
        for (int idx = tid; idx < CI_CHUNK * 3 * 258; idx += 512) {
            int ci = idx / (3 * 258);
            int rem = idx - ci * (3 * 258);
            int r = rem / 258;
            int col = rem - r * 258;
            int hr = h + r - 1;
            float v = 0.f;
            if (col >= 1 && col <= 256 && hr >= 0 && hr < Hv) {
                v = x[((size_t)(b * Cv + cc * CI_CHUNK + ci) * Hv + hr) * Wv + (col - 1)];
            }
            xs[idx] = v;
        }
        // ---- load weights, transposed to [ci9][cout] ----
        for (int idx = tid; idx < CI_CHUNK * 9 * 64; idx += 512) {
            int cout = idx & 63;
            int r9 = idx >> 6;                 // ci*9 + dh*3 + dw
            int ci = r9 / 9;
            int k9 = r9 - ci * 9;
            ws[idx] = wv[(size_t)cout * (Cv * 9) + (cc * CI_CHUNK + ci) * 9 + k9];
        }
        __syncthreads();

        // ---- compute ----
        #pragma unroll 1
        for (int ci = 0; ci < CI_CHUNK; ci++) {
            #pragma unroll
            for (int dh = 0; dh < 3; dh++) {
                const float* xrow = &xs[(ci * 3 + dh) * 258];
                unsigned long long v[4][3];
                #pragma unroll
                for (int a = 0; a < 4; a++) {
                    int base = tx + 32 * a;
                    #pragma unroll
                    for (int dw = 0; dw < 3; dw++) {
                        v[a][dw] = pk2(xrow[base + dw], xrow[base + 128 + dw]);
                    }
                }
                const float* wrow = &ws[(ci * 9 + dh * 3) * 64 + cbase];
                #pragma unroll
                for (int k = 0; k < 4; k++) {
                    #pragma unroll
                    for (int dw = 0; dw < 3; dw++) {
                        float wt = wrow[dw * 64 + k];
                        unsigned long long w2 = pk2(wt, wt);
                        #pragma unroll
                        for (int a = 0; a < 4; a++) {
                            acc[k][a] = fma2(v[a][dw], w2, acc[k][a]);
                        }
                    }
                }
            }
        }
    }

    // ---- epilogue: scores * fv + residual + BN + relu ----
    #pragma unroll
    for (int k = 0; k < 4; k++) {
        int c = cbase + k;
        float inv = gamma[c] * rsqrtf(rvar[c] + EPSV);
        float alpha = g_scores[b * Cv + c] * inv;
        float bias = beta[c] - rmean[c] * inv;
        const float* xrow = x + ((size_t)(b * Cv + c) * Hv + h) * Wv;
        float* orow = out + ((size_t)(b * Cv + c) * Hv + h) * Wv;
        #pragma unroll
        for (int a = 0; a < 4; a++) {
            float flo, fhi;
            unpk2(acc[k][a], flo, fhi);
            int wlo = tx + 32 * a;
            int whi = wlo + 128;
            float olo = fmaf(alpha, flo, fmaf(inv, xrow[wlo], bias));
            float ohi = fmaf(alpha, fhi, fmaf(inv, xrow[whi], bias));
            orow[wlo] = fmaxf(olo, 0.f);
            orow[whi] = fmaxf(ohi, 0.f);
        }
    }
}

// ---------------- launch ----------------
extern "C" void kernel_launch(void* const* d_in, const int* in_sizes, int n_in,
                              void* d_out, int out_size) {
    const float* x     = (const float*)d_in[0];
    const float* wq    = (const float*)d_in[1];
    const float* wk    = (const float*)d_in[2];
    const float* wv    = (const float*)d_in[3];
    const float* gamma = (const float*)d_in[4];
    const float* beta  = (const float*)d_in[5];
    const float* rmean = (const float*)d_in[6];
    const float* rvar  = (const float*)d_in[7];
    float* out = (float*)d_out;

    k_colsum<<<Bv * Cv, 256>>>(x);
    k_fsum<<<dim3(Cv, Bv), 256>>>(x, wq, wk);
    k_softmax<<<Bv, 64>>>();
    k_convv<<<dim3(Hv, Bv), 512>>>(x, wv, gamma, beta, rmean, rvar, out);
}